// round 5
// baseline (speedup 1.0000x reference)
#include <cuda_runtime.h>
#include <math.h>

// Problem dims (fixed by the dataset)
constexpr int B  = 4;
constexpr int L  = 2048;
constexpr int D  = 1024;
constexpr int DH = 2048;
constexpr int M_TOT = B * L;        // 8192

// Scan chunking
constexpr int NC = 16;              // chunks along time
constexpr int CL = L / NC;          // 128

// GEMM tiling
constexpr int BM = 128;
constexpr int BN = 128;
constexpr int BK = 16;
constexpr int TM = 8;
constexpr int TN = 8;
constexpr int GEMM_THREADS = 256;

// Scratch (device globals: allocation-free). Kernels reference these symbols
// directly so kernel_launch makes NO runtime API calls besides launches.
__device__ float  g_h[(size_t)M_TOT * DH];          // 64 MB: h, then silu(a) in-place
__device__ float2 g_Z[B * NC * DH];                 // per-chunk local sums
__device__ float2 g_T[B * NC * DH];                 // per-chunk entry states

// ---------------------------------------------------------------------------
// C[M,N] = A[M,K] * B[N,K]^T + bias[N]   (row-major, K contiguous)
// MODE 0: A = param x,  C = g_h   (GEMM1)
// MODE 1: A = g_h,      C = param (GEMM2)
// ---------------------------------------------------------------------------
template <int MODE>
__global__ __launch_bounds__(GEMM_THREADS)
void sgemm_nt_bias(const float* __restrict__ Aparam,
                   const float* __restrict__ Bm,
                   const float* __restrict__ bias,
                   float* __restrict__ Cparam,
                   int M, int N, int K)
{
    __shared__ float As[BK][BM + 4];
    __shared__ float Bs[BK][BN + 4];

    const float* A = (MODE == 0) ? Aparam : (const float*)g_h;
    float*       C = (MODE == 0) ? (float*)g_h : Cparam;

    const int tid = threadIdx.x;
    const int bm  = blockIdx.y * BM;
    const int bn  = blockIdx.x * BN;

    // Tile-loading indices: each tile is 128 rows x 16 k = 128 x 4 float4.
    const int lrow = tid >> 2;            // 0..63
    const int lcol = (tid & 3) * 4;       // k offset {0,4,8,12}

    // Compute mapping: 16x16 thread grid of 8x8 micro-tiles
    const int tr = (tid >> 4) * TM;       // row offset in tile
    const int tc = (tid & 15) * TN;       // col offset in tile

    float acc[TM][TN];
#pragma unroll
    for (int i = 0; i < TM; i++)
#pragma unroll
        for (int j = 0; j < TN; j++) acc[i][j] = 0.f;

    const float* Ap = A  + (size_t)bm * K;
    const float* Bp = Bm + (size_t)bn * K;

    for (int k0 = 0; k0 < K; k0 += BK) {
#pragma unroll
        for (int s = 0; s < 2; s++) {
            int r = lrow + s * 64;
            float4 va = *reinterpret_cast<const float4*>(Ap + (size_t)r * K + k0 + lcol);
            As[lcol + 0][r] = va.x; As[lcol + 1][r] = va.y;
            As[lcol + 2][r] = va.z; As[lcol + 3][r] = va.w;
            float4 vb = *reinterpret_cast<const float4*>(Bp + (size_t)r * K + k0 + lcol);
            Bs[lcol + 0][r] = vb.x; Bs[lcol + 1][r] = vb.y;
            Bs[lcol + 2][r] = vb.z; Bs[lcol + 3][r] = vb.w;
        }
        __syncthreads();

#pragma unroll
        for (int k = 0; k < BK; k++) {
            float a[TM], b[TN];
            // vectorized shared reads (tr/tc are multiples of 8; pad=4 keeps 16B align)
            *reinterpret_cast<float4*>(a)     = *reinterpret_cast<const float4*>(&As[k][tr]);
            *reinterpret_cast<float4*>(a + 4) = *reinterpret_cast<const float4*>(&As[k][tr + 4]);
            *reinterpret_cast<float4*>(b)     = *reinterpret_cast<const float4*>(&Bs[k][tc]);
            *reinterpret_cast<float4*>(b + 4) = *reinterpret_cast<const float4*>(&Bs[k][tc + 4]);
#pragma unroll
            for (int i = 0; i < TM; i++)
#pragma unroll
                for (int j = 0; j < TN; j++)
                    acc[i][j] += a[i] * b[j];
        }
        __syncthreads();
    }

#pragma unroll
    for (int i = 0; i < TM; i++) {
        size_t m = (size_t)(bm + tr + i);
#pragma unroll
        for (int j = 0; j < TN; j += 4) {
            float4 v;
            v.x = acc[i][j + 0] + bias[bn + tc + j + 0];
            v.y = acc[i][j + 1] + bias[bn + tc + j + 1];
            v.z = acc[i][j + 2] + bias[bn + tc + j + 2];
            v.w = acc[i][j + 3] + bias[bn + tc + j + 3];
            *reinterpret_cast<float4*>(C + m * N + bn + tc + j) = v;
        }
    }
}

// ---------------------------------------------------------------------------
// Scan helpers: normalized pole p = (pr,pi)/|p| * exp(-|p|)
// ---------------------------------------------------------------------------
__device__ __forceinline__ void load_pole(const float* phz, int c, float& Pr, float& Pi)
{
    float pr = phz[2 * c], pi = phz[2 * c + 1];
    float pa = sqrtf(pr * pr + pi * pi);
    float s  = expf(-pa) / pa;
    Pr = pr * s; Pi = pi * s;
}

// Pass 1: per-chunk local contribution Z_j = sum_i p^{CL-1-i} * p0 * h[j*CL+i]
__global__ void scan_chunks(const float* __restrict__ phz,
                            const float* __restrict__ phz0)
{
    int idx = blockIdx.x * blockDim.x + threadIdx.x;   // (b*NC + j)*DH + c
    int c  = idx % DH;
    int bj = idx / DH;
    int j  = bj % NC;
    int b  = bj / NC;

    float Pr, Pi;
    load_pole(phz, c, Pr, Pi);
    float p0r = phz0[2 * c], p0i = phz0[2 * c + 1];

    const float* hp = g_h + ((size_t)b * L + (size_t)j * CL) * DH + c;
    float zr = 0.f, zi = 0.f;
#pragma unroll 8
    for (int i = 0; i < CL; i++) {
        float hv = hp[(size_t)i * DH];
        float nr = fmaf(Pr, zr, fmaf(-Pi, zi, p0r * hv));
        float ni = fmaf(Pr, zi, fmaf( Pi, zr, p0i * hv));
        zr = nr; zi = ni;
    }
    g_Z[idx] = make_float2(zr, zi);
}

// Pass 2: chunk entry states  T_in(0)=last;  T_in(j+1) = p^CL * T_in(j) + Z_j
__global__ void combine_chunks(const float* __restrict__ phz,
                               const float* __restrict__ last_re,
                               const float* __restrict__ last_im)
{
    int idx = blockIdx.x * blockDim.x + threadIdx.x;   // b*DH + c
    int c = idx % DH;
    int b = idx / DH;

    float Pr, Pi;
    load_pole(phz, c, Pr, Pi);

    // A = p^CL, CL = 128 = 2^7 (repeated squaring in double for safety)
    double ar = (double)Pr, ai = (double)Pi;
#pragma unroll
    for (int s = 0; s < 7; s++) {
        double nr = ar * ar - ai * ai;
        double ni = 2.0 * ar * ai;
        ar = nr; ai = ni;
    }
    float Ar = (float)ar, Ai = (float)ai;

    float Tr = last_re[idx], Ti = last_im[idx];
#pragma unroll
    for (int j = 0; j < NC; j++) {
        int zi_idx = (b * NC + j) * DH + c;
        g_T[zi_idx] = make_float2(Tr, Ti);
        float2 z = g_Z[zi_idx];
        float nr = fmaf(Ar, Tr, fmaf(-Ai, Ti, z.x));
        float ni = fmaf(Ar, Ti, fmaf( Ai, Tr, z.y));
        Tr = nr; Ti = ni;
    }
}

// Pass 3: replay chunk with entry state, SiLU(Re(T)) written in-place over h
__global__ void apply_chunks(const float* __restrict__ phz,
                             const float* __restrict__ phz0)
{
    int idx = blockIdx.x * blockDim.x + threadIdx.x;   // (b*NC + j)*DH + c
    int c  = idx % DH;
    int bj = idx / DH;
    int j  = bj % NC;
    int b  = bj / NC;

    float Pr, Pi;
    load_pole(phz, c, Pr, Pi);
    float p0r = phz0[2 * c], p0i = phz0[2 * c + 1];

    float2 t0 = g_T[idx];
    float Tr = t0.x, Ti = t0.y;

    float* hp = g_h + ((size_t)b * L + (size_t)j * CL) * DH + c;
#pragma unroll 8
    for (int i = 0; i < CL; i++) {
        float hv = hp[(size_t)i * DH];
        float nr = fmaf(Pr, Tr, fmaf(-Pi, Ti, p0r * hv));
        float ni = fmaf(Pr, Ti, fmaf( Pi, Tr, p0i * hv));
        Tr = nr; Ti = ni;
        float v = nr;
        float a = v / (1.f + expf(-v));       // SiLU
        hp[(size_t)i * DH] = a;
    }
}

// ---------------------------------------------------------------------------
extern "C" void kernel_launch(void* const* d_in, const int* in_sizes, int n_in,
                              void* d_out, int out_size)
{
    const float* x     = (const float*)d_in[0];
    const float* W_in  = (const float*)d_in[1];
    const float* b_in  = (const float*)d_in[2];
    const float* W_out = (const float*)d_in[3];
    const float* b_out = (const float*)d_in[4];
    const float* phz   = (const float*)d_in[5];
    const float* phz0  = (const float*)d_in[6];
    const float* lre   = (const float*)d_in[7];
    const float* lim   = (const float*)d_in[8];
    float* out = (float*)d_out;

    // GEMM1: h = x @ W_in^T + b_in   [8192 x 2048, K=1024] -> g_h
    {
        dim3 grid(DH / BN, M_TOT / BM);
        sgemm_nt_bias<0><<<grid, GEMM_THREADS>>>(x, W_in, b_in, nullptr, M_TOT, DH, D);
    }

    // Exact chunked complex scan + SiLU (in place over g_h)
    {
        int n_chunk_threads = B * NC * DH;     // 131072
        scan_chunks<<<n_chunk_threads / 256, 256>>>(phz, phz0);
        combine_chunks<<<(B * DH) / 256, 256>>>(phz, lre, lim);
        apply_chunks<<<n_chunk_threads / 256, 256>>>(phz, phz0);
    }

    // GEMM2: out = silu(a) @ W_out^T + b_out   [8192 x 1024, K=2048] <- g_h
    {
        dim3 grid(D / BN, M_TOT / BM);
        sgemm_nt_bias<1><<<grid, GEMM_THREADS>>>(nullptr, W_out, b_out, out, M_TOT, D, DH);
    }
}

// round 13
// speedup vs baseline: 1.8556x; 1.8556x over previous
#include <cuda_runtime.h>
#include <cuda_bf16.h>
#include <math.h>
#include <cstdint>

// ---------------------------------------------------------------- dims
constexpr int B  = 4;
constexpr int L  = 2048;
constexpr int D  = 1024;
constexpr int DH = 2048;
constexpr int M_TOT = B * L;            // 8192

// scan chunking
constexpr int NC = 32;
constexpr int CL = L / NC;              // 64

// ---------------------------------------------------------------- scratch
// NOTE: these are referenced ONLY from device code (never passed as kernel
// arguments from host code — host-side symbol addresses are invalid).
__device__ __align__(16) float          g_h  [(size_t)M_TOT * DH];
__device__ __align__(16) __nv_bfloat16  g_xh [(size_t)M_TOT * D];
__device__ __align__(16) __nv_bfloat16  g_xl [(size_t)M_TOT * D];
__device__ __align__(16) __nv_bfloat16  g_w1h[(size_t)DH * D];
__device__ __align__(16) __nv_bfloat16  g_w1l[(size_t)DH * D];
__device__ __align__(16) __nv_bfloat16  g_w2h[(size_t)D * DH];
__device__ __align__(16) __nv_bfloat16  g_w2l[(size_t)D * DH];
__device__ __align__(16) __nv_bfloat16  g_a2h[(size_t)M_TOT * DH];
__device__ __align__(16) __nv_bfloat16  g_a2l[(size_t)M_TOT * DH];
__device__ __align__(16) float2         g_Z[B * NC * DH];
__device__ __align__(16) float2         g_T[B * NC * DH];

// ---------------------------------------------------------------- PTX helpers
__device__ __forceinline__ uint32_t smem_u32(const void* p) {
    uint32_t a;
    asm("{ .reg .u64 t; cvta.to.shared.u64 t, %1; cvt.u32.u64 %0, t; }" : "=r"(a) : "l"(p));
    return a;
}
__device__ __forceinline__ void ldsm4(uint32_t* r, uint32_t addr) {
    asm volatile("ldmatrix.sync.aligned.m8n8.x4.shared.b16 {%0,%1,%2,%3}, [%4];"
                 : "=r"(r[0]), "=r"(r[1]), "=r"(r[2]), "=r"(r[3]) : "r"(addr));
}
__device__ __forceinline__ void mma16816(float* d, const uint32_t* a, const uint32_t* b) {
    asm volatile(
        "mma.sync.aligned.m16n8k16.row.col.f32.bf16.bf16.f32 "
        "{%0,%1,%2,%3}, {%4,%5,%6,%7}, {%8,%9}, {%0,%1,%2,%3};"
        : "+f"(d[0]), "+f"(d[1]), "+f"(d[2]), "+f"(d[3])
        : "r"(a[0]), "r"(a[1]), "r"(a[2]), "r"(a[3]), "r"(b[0]), "r"(b[1]));
}

// XOR swizzle for a [128 rows][16 bf16] tile (32 B/row, two 16B chunks/row).
__device__ __forceinline__ uint32_t swz(uint32_t row, uint32_t c) {
    return row * 32 + ((c ^ ((row >> 2) & 1)) << 4);
}

// ---------------------------------------------------------------- GEMM
// C[M,N] = A[M,K]*B[N,K]^T + bias[N], fp32 via bf16 hi/lo 3-term split
// (AhBh + AhBl + AlBh) on mma.sync. CTA tile 128x128, BK=16, 8 warps (4x2),
// warp tile 32x64. Double-buffered smem, global loads staged via registers.
// MODE 0: A=g_xh/g_xl,   B=g_w1h/g_w1l, C=g_h     (N=DH, K=D)
// MODE 1: A=g_a2h/g_a2l, B=g_w2h/g_w2l, C=Cparam  (N=D,  K=DH)
constexpr int TILE4 = 4096;            // one operand tile: 128 rows * 32 B
constexpr int STG   = 4 * TILE4;       // Ah,Al,Bh,Bl per stage = 16 KB

template <int MODE>
__global__ __launch_bounds__(256)
void gemm_mma_bf16x3(const float* __restrict__ bias, float* __restrict__ Cparam)
{
    constexpr int N = MODE ? D  : DH;
    constexpr int K = MODE ? DH : D;

    const __nv_bfloat16* __restrict__ Ah = MODE ? g_a2h : g_xh;
    const __nv_bfloat16* __restrict__ Al = MODE ? g_a2l : g_xl;
    const __nv_bfloat16* __restrict__ Bh = MODE ? g_w2h : g_w1h;
    const __nv_bfloat16* __restrict__ Bl = MODE ? g_w2l : g_w1l;
    float* __restrict__ C = MODE ? Cparam : g_h;

    __shared__ __align__(128) uint8_t smem[2 * STG];    // 32 KB
    const uint32_t sb = smem_u32(smem);

    const int tid  = threadIdx.x;
    const int wid  = tid >> 5;
    const int lane = tid & 31;
    const int wm   = (wid >> 1) * 32;          // warp row offset in CTA tile
    const int wn   = (wid & 1) * 64;           // warp col offset
    const int bm   = blockIdx.y * 128;
    const int bn   = blockIdx.x * 128;

    // loader mapping: thread -> (row = tid/2, 16B chunk = tid&1)
    const int lrow = tid >> 1;
    const int lc   = tid & 1;
    const uint32_t sw_st = swz(lrow, lc);
    const uint4* pAh = reinterpret_cast<const uint4*>(Ah + (size_t)(bm + lrow) * K);
    const uint4* pAl = reinterpret_cast<const uint4*>(Al + (size_t)(bm + lrow) * K);
    const uint4* pBh = reinterpret_cast<const uint4*>(Bh + (size_t)(bn + lrow) * K);
    const uint4* pBl = reinterpret_cast<const uint4*>(Bl + (size_t)(bn + lrow) * K);

    // ldmatrix source addresses (within-stage byte offsets)
    const uint32_t swA = swz(wm + (lane & 15), lane >> 4);
    const uint32_t swB = swz(wn + ((lane >> 4) << 3) + (lane & 7), (lane >> 3) & 1);

    float acc[2][8][4];
#pragma unroll
    for (int mt = 0; mt < 2; mt++)
#pragma unroll
        for (int nt = 0; nt < 8; nt++)
#pragma unroll
            for (int r = 0; r < 4; r++) acc[mt][nt][r] = 0.f;

    constexpr int NIT = K / 16;

    uint4 rAh = pAh[lc], rAl = pAl[lc], rBh = pBh[lc], rBl = pBl[lc];

    for (int i = 0; i < NIT; i++) {
        const uint32_t boff = (uint32_t)(i & 1) * STG;
        // stage registers -> smem
        *reinterpret_cast<uint4*>(smem + boff +         0 + sw_st) = rAh;
        *reinterpret_cast<uint4*>(smem + boff +  TILE4    + sw_st) = rAl;
        *reinterpret_cast<uint4*>(smem + boff + 2 * TILE4 + sw_st) = rBh;
        *reinterpret_cast<uint4*>(smem + boff + 3 * TILE4 + sw_st) = rBl;
        __syncthreads();

        // prefetch next k-slice into registers (overlaps with compute)
        if (i + 1 < NIT) {
            int o = lc + 2 * (i + 1);
            rAh = pAh[o]; rAl = pAl[o]; rBh = pBh[o]; rBl = pBl[o];
        }

        const uint32_t base = sb + boff;
        uint32_t a_h[2][4], a_l[2][4];
#pragma unroll
        for (int mt = 0; mt < 2; mt++) {
            ldsm4(a_h[mt], base +             swA + mt * 512);
            ldsm4(a_l[mt], base + TILE4     + swA + mt * 512);
        }
        uint32_t b_h[4][4], b_l[4][4];
#pragma unroll
        for (int pr = 0; pr < 4; pr++) {
            ldsm4(b_h[pr], base + 2 * TILE4 + swB + pr * 512);
            ldsm4(b_l[pr], base + 3 * TILE4 + swB + pr * 512);
        }
#pragma unroll
        for (int mt = 0; mt < 2; mt++)
#pragma unroll
            for (int pr = 0; pr < 4; pr++)
#pragma unroll
                for (int s = 0; s < 2; s++) {
                    float* d = acc[mt][pr * 2 + s];
                    mma16816(d, a_h[mt], &b_h[pr][s * 2]);
                    mma16816(d, a_h[mt], &b_l[pr][s * 2]);
                    mma16816(d, a_l[mt], &b_h[pr][s * 2]);
                }
        __syncthreads();
    }

    // epilogue: acc + bias -> C
#pragma unroll
    for (int mt = 0; mt < 2; mt++)
#pragma unroll
        for (int nt = 0; nt < 8; nt++) {
            const float* d = acc[mt][nt];
            int row = bm + wm + mt * 16 + (lane >> 2);
            int col = bn + wn + nt * 8 + (lane & 3) * 2;
            float b0 = bias[col], b1 = bias[col + 1];
            float2 v0 = {d[0] + b0, d[1] + b1};
            float2 v1 = {d[2] + b0, d[3] + b1};
            *reinterpret_cast<float2*>(C + (size_t)row * N + col)       = v0;
            *reinterpret_cast<float2*>(C + (size_t)(row + 8) * N + col) = v1;
        }
}

// ---------------------------------------------------------------- fp32 -> bf16 hi/lo split
// WHICH 0: x -> g_xh/g_xl;  1: W_in -> g_w1h/g_w1l;  2: W_out -> g_w2h/g_w2l
template <int WHICH>
__global__ void split_f32(const float* __restrict__ s)
{
    __nv_bfloat16* hi = (WHICH == 0) ? g_xh : (WHICH == 1) ? g_w1h : g_w2h;
    __nv_bfloat16* lo = (WHICH == 0) ? g_xl : (WHICH == 1) ? g_w1l : g_w2l;
    int i = (blockIdx.x * blockDim.x + threadIdx.x) * 4;
    float4 v = *reinterpret_cast<const float4*>(s + i);
    __nv_bfloat16 h0 = __float2bfloat16(v.x), h1 = __float2bfloat16(v.y);
    __nv_bfloat16 h2 = __float2bfloat16(v.z), h3 = __float2bfloat16(v.w);
    __nv_bfloat162 hp0{h0, h1}, hp1{h2, h3};
    __nv_bfloat162 lp0{__float2bfloat16(v.x - __bfloat162float(h0)),
                       __float2bfloat16(v.y - __bfloat162float(h1))};
    __nv_bfloat162 lp1{__float2bfloat16(v.z - __bfloat162float(h2)),
                       __float2bfloat16(v.w - __bfloat162float(h3))};
    *reinterpret_cast<__nv_bfloat162*>(hi + i)     = hp0;
    *reinterpret_cast<__nv_bfloat162*>(hi + i + 2) = hp1;
    *reinterpret_cast<__nv_bfloat162*>(lo + i)     = lp0;
    *reinterpret_cast<__nv_bfloat162*>(lo + i + 2) = lp1;
}

// ---------------------------------------------------------------- scan
__device__ __forceinline__ void load_pole(const float* phz, int c, float& Pr, float& Pi)
{
    float pr = phz[2 * c], pi = phz[2 * c + 1];
    float pa = sqrtf(pr * pr + pi * pi);
    float s  = expf(-pa) / pa;
    Pr = pr * s; Pi = pi * s;
}

__global__ void scan_chunks(const float* __restrict__ phz, const float* __restrict__ phz0)
{
    int idx = blockIdx.x * blockDim.x + threadIdx.x;   // (b*NC+j)*DH + c
    int c  = idx % DH;
    int bj = idx / DH;
    int j  = bj % NC;
    int b  = bj / NC;

    float Pr, Pi; load_pole(phz, c, Pr, Pi);
    float p0r = phz0[2 * c], p0i = phz0[2 * c + 1];

    const float* hp = g_h + ((size_t)b * L + (size_t)j * CL) * DH + c;
    float zr = 0.f, zi = 0.f;
#pragma unroll 8
    for (int i = 0; i < CL; i++) {
        float hv = hp[(size_t)i * DH];
        float nr = fmaf(Pr, zr, fmaf(-Pi, zi, p0r * hv));
        float ni = fmaf(Pr, zi, fmaf( Pi, zr, p0i * hv));
        zr = nr; zi = ni;
    }
    g_Z[idx] = make_float2(zr, zi);
}

__global__ void combine_chunks(const float* __restrict__ phz,
                               const float* __restrict__ last_re,
                               const float* __restrict__ last_im)
{
    int idx = blockIdx.x * blockDim.x + threadIdx.x;   // b*DH + c
    int c = idx % DH;
    int b = idx / DH;

    float Pr, Pi; load_pole(phz, c, Pr, Pi);

    // A = p^CL, CL = 64 = 2^6 (repeated squaring in double)
    double ar = (double)Pr, ai = (double)Pi;
#pragma unroll
    for (int s = 0; s < 6; s++) {
        double nr = ar * ar - ai * ai;
        double ni = 2.0 * ar * ai;
        ar = nr; ai = ni;
    }
    float Ar = (float)ar, Ai = (float)ai;

    float Tr = last_re[idx], Ti = last_im[idx];
#pragma unroll
    for (int j = 0; j < NC; j++) {
        int zi_idx = (b * NC + j) * DH + c;
        g_T[zi_idx] = make_float2(Tr, Ti);
        float2 z = g_Z[zi_idx];
        float nr = fmaf(Ar, Tr, fmaf(-Ai, Ti, z.x));
        float ni = fmaf(Ar, Ti, fmaf( Ai, Tr, z.y));
        Tr = nr; Ti = ni;
    }
}

// replay chunk; write silu result directly as bf16 hi/lo (GEMM2's A operand)
__global__ void apply_chunks(const float* __restrict__ phz, const float* __restrict__ phz0)
{
    int idx = blockIdx.x * blockDim.x + threadIdx.x;
    int c  = idx % DH;
    int bj = idx / DH;
    int j  = bj % NC;
    int b  = bj / NC;

    float Pr, Pi; load_pole(phz, c, Pr, Pi);
    float p0r = phz0[2 * c], p0i = phz0[2 * c + 1];

    float2 t0 = g_T[idx];
    float Tr = t0.x, Ti = t0.y;

    size_t base = ((size_t)b * L + (size_t)j * CL) * DH + c;
    const float* hp = g_h + base;
    __nv_bfloat16* ah = g_a2h + base;
    __nv_bfloat16* al = g_a2l + base;
#pragma unroll 8
    for (int i = 0; i < CL; i++) {
        float hv = hp[(size_t)i * DH];
        float nr = fmaf(Pr, Tr, fmaf(-Pi, Ti, p0r * hv));
        float ni = fmaf(Pr, Ti, fmaf( Pi, Tr, p0i * hv));
        Tr = nr; Ti = ni;
        float a = nr / (1.f + expf(-nr));          // SiLU
        __nv_bfloat16 h = __float2bfloat16(a);
        ah[(size_t)i * DH] = h;
        al[(size_t)i * DH] = __float2bfloat16(a - __bfloat162float(h));
    }
}

// ----------------------------------------------------------------
extern "C" void kernel_launch(void* const* d_in, const int* in_sizes, int n_in,
                              void* d_out, int out_size)
{
    const float* x     = (const float*)d_in[0];
    const float* W_in  = (const float*)d_in[1];
    const float* b_in  = (const float*)d_in[2];
    const float* W_out = (const float*)d_in[3];
    const float* b_out = (const float*)d_in[4];
    const float* phz   = (const float*)d_in[5];
    const float* phz0  = (const float*)d_in[6];
    const float* lre   = (const float*)d_in[7];
    const float* lim   = (const float*)d_in[8];
    float* out = (float*)d_out;

    // split fp32 inputs into bf16 hi/lo pairs (destinations bound in device code)
    split_f32<0><<<(M_TOT * D) / 1024, 256>>>(x);
    split_f32<1><<<(DH * D)    / 1024, 256>>>(W_in);
    split_f32<2><<<(D * DH)    / 1024, 256>>>(W_out);

    // GEMM1: h = x @ W_in^T + b_in   [8192 x 2048, K=1024] -> g_h
    gemm_mma_bf16x3<0><<<dim3(DH / 128, M_TOT / 128), 256>>>(b_in, nullptr);

    // exact chunked complex scan + SiLU (emits bf16 hi/lo for GEMM2)
    scan_chunks<<<(B * NC * DH) / 256, 256>>>(phz, phz0);
    combine_chunks<<<(B * DH) / 256, 256>>>(phz, lre, lim);
    apply_chunks<<<(B * NC * DH) / 256, 256>>>(phz, phz0);

    // GEMM2: out = silu(conv) @ W_out^T + b_out   [8192 x 1024, K=2048]
    gemm_mma_bf16x3<1><<<dim3(D / 128, M_TOT / 128), 256>>>(b_out, out);
}

// round 14
// speedup vs baseline: 2.4253x; 1.3070x over previous
#include <cuda_runtime.h>
#include <cuda_bf16.h>
#include <math.h>
#include <cstdint>

// ---------------------------------------------------------------- dims
constexpr int B  = 4;
constexpr int L  = 2048;
constexpr int D  = 1024;
constexpr int DH = 2048;
constexpr int M_TOT = B * L;            // 8192

// scan chunking
constexpr int NC = 32;
constexpr int CL = L / NC;              // 64

// ---------------------------------------------------------------- scratch
// Referenced ONLY from device code (host-side symbol addresses are invalid).
__device__ __align__(16) float          g_h  [(size_t)M_TOT * DH];
__device__ __align__(16) __nv_bfloat16  g_xh [(size_t)M_TOT * D];
__device__ __align__(16) __nv_bfloat16  g_xl [(size_t)M_TOT * D];
__device__ __align__(16) __nv_bfloat16  g_w1h[(size_t)DH * D];
__device__ __align__(16) __nv_bfloat16  g_w1l[(size_t)DH * D];
__device__ __align__(16) __nv_bfloat16  g_w2h[(size_t)D * DH];
__device__ __align__(16) __nv_bfloat16  g_w2l[(size_t)D * DH];
__device__ __align__(16) __nv_bfloat16  g_a2h[(size_t)M_TOT * DH];
__device__ __align__(16) __nv_bfloat16  g_a2l[(size_t)M_TOT * DH];
__device__ __align__(16) float2         g_Z[B * NC * DH];
__device__ __align__(16) float2         g_T[B * NC * DH];

// ---------------------------------------------------------------- PTX helpers
__device__ __forceinline__ uint32_t smem_u32(const void* p) {
    uint32_t a;
    asm("{ .reg .u64 t; cvta.to.shared.u64 t, %1; cvt.u32.u64 %0, t; }" : "=r"(a) : "l"(p));
    return a;
}
__device__ __forceinline__ void cp16(uint32_t s, const void* g) {
    asm volatile("cp.async.cg.shared.global [%0], [%1], 16;" :: "r"(s), "l"(g));
}
#define CP_COMMIT() asm volatile("cp.async.commit_group;" ::: "memory")
#define CP_WAIT1()  asm volatile("cp.async.wait_group 1;" ::: "memory")

__device__ __forceinline__ void ldsm4(uint32_t* r, uint32_t addr) {
    asm volatile("ldmatrix.sync.aligned.m8n8.x4.shared.b16 {%0,%1,%2,%3}, [%4];"
                 : "=r"(r[0]), "=r"(r[1]), "=r"(r[2]), "=r"(r[3]) : "r"(addr));
}
__device__ __forceinline__ void mma16816(float* d, const uint32_t* a, const uint32_t* b) {
    asm volatile(
        "mma.sync.aligned.m16n8k16.row.col.f32.bf16.bf16.f32 "
        "{%0,%1,%2,%3}, {%4,%5,%6,%7}, {%8,%9}, {%0,%1,%2,%3};"
        : "+f"(d[0]), "+f"(d[1]), "+f"(d[2]), "+f"(d[3])
        : "r"(a[0]), "r"(a[1]), "r"(a[2]), "r"(a[3]), "r"(b[0]), "r"(b[1]));
}

// XOR swizzle for a [128 rows][16 bf16] tile (32 B/row, two 16B chunks/row).
__device__ __forceinline__ uint32_t swz(uint32_t row, uint32_t c) {
    return row * 32 + ((c ^ ((row >> 2) & 1)) << 4);
}

// ---------------------------------------------------------------- GEMM
// C[M,N] = A[M,K]*B[N,K]^T + bias[N], fp32 via bf16 hi/lo 3-term split
// (AhBh + AhBl + AlBh) on mma.sync. CTA tile 128x128, BK=16, 8 warps (4x2),
// warp tile 32x64. 3-stage cp.async pipeline, ONE syncthreads per k-slice.
// MODE 0: A=g_xh/g_xl,   B=g_w1h/g_w1l, C=g_h     (N=DH, K=D)
// MODE 1: A=g_a2h/g_a2l, B=g_w2h/g_w2l, C=Cparam  (N=D,  K=DH)
constexpr int TILE4  = 4096;           // one operand tile: 128 rows * 32 B
constexpr int STG    = 4 * TILE4;      // Ah,Al,Bh,Bl per stage = 16 KB
constexpr int NSTAGE = 3;              // 48 KB static smem

template <int MODE>
__global__ __launch_bounds__(256)
void gemm_mma_bf16x3(const float* __restrict__ bias, float* __restrict__ Cparam)
{
    constexpr int N = MODE ? D  : DH;
    constexpr int K = MODE ? DH : D;

    const __nv_bfloat16* __restrict__ Ah = MODE ? g_a2h : g_xh;
    const __nv_bfloat16* __restrict__ Al = MODE ? g_a2l : g_xl;
    const __nv_bfloat16* __restrict__ Bh = MODE ? g_w2h : g_w1h;
    const __nv_bfloat16* __restrict__ Bl = MODE ? g_w2l : g_w1l;
    float* __restrict__ C = MODE ? Cparam : g_h;

    __shared__ __align__(128) uint8_t smem[NSTAGE * STG];   // 48 KB
    const uint32_t sb = smem_u32(smem);

    const int tid  = threadIdx.x;
    const int wid  = tid >> 5;
    const int lane = tid & 31;
    const int wm   = (wid >> 1) * 32;          // warp row offset in CTA tile
    const int wn   = (wid & 1) * 64;           // warp col offset
    const int bm   = blockIdx.y * 128;
    const int bn   = blockIdx.x * 128;

    // loader mapping: thread -> (row = tid/2, 16B chunk = tid&1)
    const int lrow = tid >> 1;
    const int lc   = tid & 1;
    const uint32_t sw_st = swz(lrow, lc);
    const __nv_bfloat16* gAh = Ah + (size_t)(bm + lrow) * K + lc * 8;
    const __nv_bfloat16* gAl = Al + (size_t)(bm + lrow) * K + lc * 8;
    const __nv_bfloat16* gBh = Bh + (size_t)(bn + lrow) * K + lc * 8;
    const __nv_bfloat16* gBl = Bl + (size_t)(bn + lrow) * K + lc * 8;

    // ldmatrix source addresses (within-stage byte offsets)
    const uint32_t swA = swz(wm + (lane & 15), lane >> 4);
    const uint32_t swB = swz(wn + ((lane >> 4) << 3) + (lane & 7), (lane >> 3) & 1);

    float acc[2][8][4];
#pragma unroll
    for (int mt = 0; mt < 2; mt++)
#pragma unroll
        for (int nt = 0; nt < 8; nt++)
#pragma unroll
            for (int r = 0; r < 4; r++) acc[mt][nt][r] = 0.f;

    constexpr int NIT = K / 16;

    auto load_stage = [&](int i, int st) {
        uint32_t base = sb + st * STG;
        int k0 = i * 16;
        cp16(base +         0 + sw_st, gAh + k0);
        cp16(base +  TILE4    + sw_st, gAl + k0);
        cp16(base + 2 * TILE4 + sw_st, gBh + k0);
        cp16(base + 3 * TILE4 + sw_st, gBl + k0);
        CP_COMMIT();
    };

    load_stage(0, 0);
    load_stage(1, 1);

    for (int i = 0; i < NIT; i++) {
        const int st = i % NSTAGE;
        const uint32_t base = sb + st * STG;
        CP_WAIT1();              // stage i landed (newest 1 group may be in flight)
        __syncthreads();         // single barrier per slice (reuse distance = 3)

        // issue next stage's loads immediately — they fly during the mma chain
        if (i + 2 < NIT) load_stage(i + 2, (i + 2) % NSTAGE);
        else             CP_COMMIT();      // empty group keeps wait accounting exact

        uint32_t a_h[2][4], a_l[2][4];
#pragma unroll
        for (int mt = 0; mt < 2; mt++) {
            ldsm4(a_h[mt], base +             swA + mt * 512);
            ldsm4(a_l[mt], base + TILE4     + swA + mt * 512);
        }
#pragma unroll
        for (int pr = 0; pr < 4; pr++) {
            uint32_t b_h[4], b_l[4];
            ldsm4(b_h, base + 2 * TILE4 + swB + pr * 512);
            ldsm4(b_l, base + 3 * TILE4 + swB + pr * 512);
#pragma unroll
            for (int mt = 0; mt < 2; mt++)
#pragma unroll
                for (int s = 0; s < 2; s++) {
                    float* d = acc[mt][pr * 2 + s];
                    mma16816(d, a_h[mt], &b_h[s * 2]);
                    mma16816(d, a_h[mt], &b_l[s * 2]);
                    mma16816(d, a_l[mt], &b_h[s * 2]);
                }
        }
    }

    // epilogue: acc + bias -> C
#pragma unroll
    for (int mt = 0; mt < 2; mt++)
#pragma unroll
        for (int nt = 0; nt < 8; nt++) {
            const float* d = acc[mt][nt];
            int row = bm + wm + mt * 16 + (lane >> 2);
            int col = bn + wn + nt * 8 + (lane & 3) * 2;
            float b0 = bias[col], b1 = bias[col + 1];
            float2 v0 = {d[0] + b0, d[1] + b1};
            float2 v1 = {d[2] + b0, d[3] + b1};
            *reinterpret_cast<float2*>(C + (size_t)row * N + col)       = v0;
            *reinterpret_cast<float2*>(C + (size_t)(row + 8) * N + col) = v1;
        }
}

// ---------------------------------------------------------------- fp32 -> bf16 hi/lo split
// WHICH 0: x -> g_xh/g_xl;  1: W_in -> g_w1h/g_w1l;  2: W_out -> g_w2h/g_w2l
template <int WHICH>
__global__ void split_f32(const float* __restrict__ s)
{
    __nv_bfloat16* hi = (WHICH == 0) ? g_xh : (WHICH == 1) ? g_w1h : g_w2h;
    __nv_bfloat16* lo = (WHICH == 0) ? g_xl : (WHICH == 1) ? g_w1l : g_w2l;
    int i = (blockIdx.x * blockDim.x + threadIdx.x) * 4;
    float4 v = *reinterpret_cast<const float4*>(s + i);
    __nv_bfloat16 h0 = __float2bfloat16(v.x), h1 = __float2bfloat16(v.y);
    __nv_bfloat16 h2 = __float2bfloat16(v.z), h3 = __float2bfloat16(v.w);
    __nv_bfloat162 hp0{h0, h1}, hp1{h2, h3};
    __nv_bfloat162 lp0{__float2bfloat16(v.x - __bfloat162float(h0)),
                       __float2bfloat16(v.y - __bfloat162float(h1))};
    __nv_bfloat162 lp1{__float2bfloat16(v.z - __bfloat162float(h2)),
                       __float2bfloat16(v.w - __bfloat162float(h3))};
    *reinterpret_cast<__nv_bfloat162*>(hi + i)     = hp0;
    *reinterpret_cast<__nv_bfloat162*>(hi + i + 2) = hp1;
    *reinterpret_cast<__nv_bfloat162*>(lo + i)     = lp0;
    *reinterpret_cast<__nv_bfloat162*>(lo + i + 2) = lp1;
}

// ---------------------------------------------------------------- scan
__device__ __forceinline__ void load_pole(const float* phz, int c, float& Pr, float& Pi)
{
    float pr = phz[2 * c], pi = phz[2 * c + 1];
    float pa = sqrtf(pr * pr + pi * pi);
    float s  = expf(-pa) / pa;
    Pr = pr * s; Pi = pi * s;
}

__global__ void scan_chunks(const float* __restrict__ phz, const float* __restrict__ phz0)
{
    int idx = blockIdx.x * blockDim.x + threadIdx.x;   // (b*NC+j)*DH + c
    int c  = idx % DH;
    int bj = idx / DH;
    int j  = bj % NC;
    int b  = bj / NC;

    float Pr, Pi; load_pole(phz, c, Pr, Pi);
    float p0r = phz0[2 * c], p0i = phz0[2 * c + 1];

    const float* hp = g_h + ((size_t)b * L + (size_t)j * CL) * DH + c;
    float zr = 0.f, zi = 0.f;
#pragma unroll 8
    for (int i = 0; i < CL; i++) {
        float hv = hp[(size_t)i * DH];
        float nr = fmaf(Pr, zr, fmaf(-Pi, zi, p0r * hv));
        float ni = fmaf(Pr, zi, fmaf( Pi, zr, p0i * hv));
        zr = nr; zi = ni;
    }
    g_Z[idx] = make_float2(zr, zi);
}

__global__ void combine_chunks(const float* __restrict__ phz,
                               const float* __restrict__ last_re,
                               const float* __restrict__ last_im)
{
    int idx = blockIdx.x * blockDim.x + threadIdx.x;   // b*DH + c
    int c = idx % DH;
    int b = idx / DH;

    float Pr, Pi; load_pole(phz, c, Pr, Pi);

    // A = p^CL, CL = 64 = 2^6 (repeated squaring in double)
    double ar = (double)Pr, ai = (double)Pi;
#pragma unroll
    for (int s = 0; s < 6; s++) {
        double nr = ar * ar - ai * ai;
        double ni = 2.0 * ar * ai;
        ar = nr; ai = ni;
    }
    float Ar = (float)ar, Ai = (float)ai;

    float Tr = last_re[idx], Ti = last_im[idx];
#pragma unroll
    for (int j = 0; j < NC; j++) {
        int zi_idx = (b * NC + j) * DH + c;
        g_T[zi_idx] = make_float2(Tr, Ti);
        float2 z = g_Z[zi_idx];
        float nr = fmaf(Ar, Tr, fmaf(-Ai, Ti, z.x));
        float ni = fmaf(Ar, Ti, fmaf( Ai, Tr, z.y));
        Tr = nr; Ti = ni;
    }
}

// replay chunk; write silu result directly as bf16 hi/lo (GEMM2's A operand)
__global__ void apply_chunks(const float* __restrict__ phz, const float* __restrict__ phz0)
{
    int idx = blockIdx.x * blockDim.x + threadIdx.x;
    int c  = idx % DH;
    int bj = idx / DH;
    int j  = bj % NC;
    int b  = bj / NC;

    float Pr, Pi; load_pole(phz, c, Pr, Pi);
    float p0r = phz0[2 * c], p0i = phz0[2 * c + 1];

    float2 t0 = g_T[idx];
    float Tr = t0.x, Ti = t0.y;

    size_t base = ((size_t)b * L + (size_t)j * CL) * DH + c;
    const float* hp = g_h + base;
    __nv_bfloat16* ah = g_a2h + base;
    __nv_bfloat16* al = g_a2l + base;
#pragma unroll 8
    for (int i = 0; i < CL; i++) {
        float hv = hp[(size_t)i * DH];
        float nr = fmaf(Pr, Tr, fmaf(-Pi, Ti, p0r * hv));
        float ni = fmaf(Pr, Ti, fmaf( Pi, Tr, p0i * hv));
        Tr = nr; Ti = ni;
        float a = nr / (1.f + expf(-nr));          // SiLU
        __nv_bfloat16 h = __float2bfloat16(a);
        ah[(size_t)i * DH] = h;
        al[(size_t)i * DH] = __float2bfloat16(a - __bfloat162float(h));
    }
}

// ----------------------------------------------------------------
extern "C" void kernel_launch(void* const* d_in, const int* in_sizes, int n_in,
                              void* d_out, int out_size)
{
    const float* x     = (const float*)d_in[0];
    const float* W_in  = (const float*)d_in[1];
    const float* b_in  = (const float*)d_in[2];
    const float* W_out = (const float*)d_in[3];
    const float* b_out = (const float*)d_in[4];
    const float* phz   = (const float*)d_in[5];
    const float* phz0  = (const float*)d_in[6];
    const float* lre   = (const float*)d_in[7];
    const float* lim   = (const float*)d_in[8];
    float* out = (float*)d_out;

    // split fp32 inputs into bf16 hi/lo pairs (destinations bound in device code)
    split_f32<0><<<(M_TOT * D) / 1024, 256>>>(x);
    split_f32<1><<<(DH * D)    / 1024, 256>>>(W_in);
    split_f32<2><<<(D * DH)    / 1024, 256>>>(W_out);

    // GEMM1: h = x @ W_in^T + b_in   [8192 x 2048, K=1024] -> g_h
    gemm_mma_bf16x3<0><<<dim3(DH / 128, M_TOT / 128), 256>>>(b_in, nullptr);

    // exact chunked complex scan + SiLU (emits bf16 hi/lo for GEMM2)
    scan_chunks<<<(B * NC * DH) / 256, 256>>>(phz, phz0);
    combine_chunks<<<(B * DH) / 256, 256>>>(phz, lre, lim);
    apply_chunks<<<(B * NC * DH) / 256, 256>>>(phz, phz0);

    // GEMM2: out = silu(conv) @ W_out^T + b_out   [8192 x 1024, K=2048]
    gemm_mma_bf16x3<1><<<dim3(D / 128, M_TOT / 128), 256>>>(b_out, out);
}